// round 4
// baseline (speedup 1.0000x reference)
#include <cuda_runtime.h>
#include <cstddef>

#define NN 50000
#define NE 800000
#define C_IN 512
#define C_H 512
#define C_OUT 256

// ---------------- scratch (static device memory; no allocations) ----------------
__device__ int   g_is64;                 // 1 if edge_index buffer is int64-laid-out
__device__ int   g_cnt[NN];
__device__ int   g_cursor[NN];
__device__ float g_dinv[NN];
__device__ int   g_rowstart[NN + 1];
__device__ int   g_csr_src[NE];
__device__ float g_csr_w[NE];
__device__ float g_t[(size_t)NN * C_H];          // GEMM output buffer (t = h @ W)
__device__ float g_h[2][(size_t)NN * C_H];       // ping/pong hidden state

// read edge endpoint robustly under either dtype layout
__device__ __forceinline__ int edge_src(const int* ei, int e, int is64) {
    return is64 ? ei[2 * e] : ei[e];
}
__device__ __forceinline__ int edge_dst(const int* ei, int e, int is64) {
    return is64 ? ei[2 * (NE + e)] : ei[NE + e];
}

// ---------------- dtype-layout probe ----------------
// If the buffer holds little-endian int64 values (< 2^31), every odd 32-bit
// word is 0. OR-reduce the first 4096 odd words; all-zero => int64 layout.
__global__ void k_detect(const int* __restrict__ ei) {
    __shared__ int s_or[256];
    int acc = 0;
    for (int i = threadIdx.x; i < 4096; i += 256) acc |= ei[2 * i + 1];
    s_or[threadIdx.x] = acc;
    __syncthreads();
    for (int off = 128; off > 0; off >>= 1) {
        if (threadIdx.x < off) s_or[threadIdx.x] |= s_or[threadIdx.x + off];
        __syncthreads();
    }
    if (threadIdx.x == 0) g_is64 = (s_or[0] == 0) ? 1 : 0;
}

// ---------------- graph preprocessing ----------------
__global__ void k_zero() {
    int i = blockIdx.x * blockDim.x + threadIdx.x;
    if (i < NN) { g_cnt[i] = 0; g_cursor[i] = 0; }
}

__global__ void k_count(const int* __restrict__ ei) {
    int e = blockIdx.x * blockDim.x + threadIdx.x;
    if (e < NE) {
        int d = edge_dst(ei, e, g_is64);
        if ((unsigned)d < NN) atomicAdd(&g_cnt[d], 1);
    }
}

__global__ void k_dinv() {
    int i = blockIdx.x * blockDim.x + threadIdx.x;
    if (i < NN) {
        float deg = (float)(g_cnt[i] + 1);   // +1 self loop
        g_dinv[i] = rsqrtf(deg);
    }
}

// single-block exclusive scan of g_cnt -> g_rowstart
__global__ void k_scan() {
    __shared__ int s[1024];
    int carry = 0;
    for (int base = 0; base < NN; base += 1024) {
        int i = base + (int)threadIdx.x;
        int v = (i < NN) ? g_cnt[i] : 0;
        s[threadIdx.x] = v;
        __syncthreads();
        #pragma unroll
        for (int off = 1; off < 1024; off <<= 1) {
            int t = (threadIdx.x >= (unsigned)off) ? s[threadIdx.x - off] : 0;
            __syncthreads();
            s[threadIdx.x] += t;
            __syncthreads();
        }
        if (i < NN) g_rowstart[i] = carry + s[threadIdx.x] - v;  // exclusive
        carry += s[1023];
        __syncthreads();
    }
    if (threadIdx.x == 0) g_rowstart[NN] = carry;
}

__global__ void k_scatter(const int* __restrict__ ei) {
    int e = blockIdx.x * blockDim.x + threadIdx.x;
    if (e < NE) {
        int is64 = g_is64;
        int s = edge_src(ei, e, is64);
        int d = edge_dst(ei, e, is64);
        if ((unsigned)s < NN && (unsigned)d < NN) {
            int pos = g_rowstart[d] + atomicAdd(&g_cursor[d], 1);
            g_csr_src[pos] = s;
            g_csr_w[pos]   = g_dinv[s] * g_dinv[d];
        }
    }
}

// ---------------- fp32 GEMM: g_t[M,N] = A[M,K] @ B[K,N] ----------------
// A = (asel >= 0) ? g_h[asel] : Aext.  Output always g_t.
// 128x128 block tile, BK=8, 8x8 per thread, 256 threads.
__global__ __launch_bounds__(256, 2)
void k_sgemm(const float* __restrict__ Aext, int asel,
             const float* __restrict__ B, int M, int N, int K) {
    const float* __restrict__ A = (asel >= 0) ? &g_h[asel][0] : Aext;
    float* __restrict__ C = &g_t[0];

    __shared__ float As[8][128];
    __shared__ float Bs[8][128];

    const int tid = threadIdx.x;
    const int tx = tid & 15;          // 0..15  (N direction)
    const int ty = tid >> 4;          // 0..15  (M direction)

    const int aRow = tid >> 1;        // 0..127
    const int aCol = (tid & 1) * 4;   // 0 or 4
    const int bRow = tid >> 5;        // 0..7
    const int bCol = (tid & 31) * 4;  // 0..124

    const int mBase = blockIdx.y * 128;
    const int nBase = blockIdx.x * 128;
    const int mRow  = mBase + aRow;
    const bool aOk  = (mRow < M);

    const float* Ab = A + (size_t)mRow * K;
    const float* Bb = B + nBase;

    float acc[8][8];
    #pragma unroll
    for (int i = 0; i < 8; i++)
        #pragma unroll
        for (int j = 0; j < 8; j++) acc[i][j] = 0.0f;

    for (int k0 = 0; k0 < K; k0 += 8) {
        float4 av = aOk ? *(const float4*)(Ab + k0 + aCol)
                        : make_float4(0.f, 0.f, 0.f, 0.f);
        As[aCol + 0][aRow] = av.x;
        As[aCol + 1][aRow] = av.y;
        As[aCol + 2][aRow] = av.z;
        As[aCol + 3][aRow] = av.w;

        float4 bv = *(const float4*)(Bb + (size_t)(k0 + bRow) * N + bCol);
        *(float4*)&Bs[bRow][bCol] = bv;
        __syncthreads();

        #pragma unroll
        for (int k = 0; k < 8; k++) {
            float4 a0 = *(const float4*)&As[k][ty * 8];
            float4 a1 = *(const float4*)&As[k][ty * 8 + 4];
            float4 b0 = *(const float4*)&Bs[k][tx * 8];
            float4 b1 = *(const float4*)&Bs[k][tx * 8 + 4];
            float a[8] = {a0.x, a0.y, a0.z, a0.w, a1.x, a1.y, a1.z, a1.w};
            float b[8] = {b0.x, b0.y, b0.z, b0.w, b1.x, b1.y, b1.z, b1.w};
            #pragma unroll
            for (int i = 0; i < 8; i++)
                #pragma unroll
                for (int j = 0; j < 8; j++)
                    acc[i][j] = fmaf(a[i], b[j], acc[i][j]);
        }
        __syncthreads();
    }

    #pragma unroll
    for (int i = 0; i < 8; i++) {
        int r = mBase + ty * 8 + i;
        if (r < M) {
            float* Crow = C + (size_t)r * N + nBase + tx * 8;
            *(float4*)(Crow)     = make_float4(acc[i][0], acc[i][1], acc[i][2], acc[i][3]);
            *(float4*)(Crow + 4) = make_float4(acc[i][4], acc[i][5], acc[i][6], acc[i][7]);
        }
    }
}

// ---------------- SpMM ----------------
// out[d] = relu?( sum_e w_e * t[src_e] + dinv[d]^2 * t[d] + bias ) (+ residual g_h[rsel])
// Output: OutExt if non-null else g_h[osel]. Input feature matrix: g_t.
template <int C, bool RELU, bool RES>
__global__ void k_spmm(const float* __restrict__ bias,
                       int rsel, float* __restrict__ OutExt, int osel) {
    constexpr int NT = C / 4;           // threads per block (128 or 64)
    const float* __restrict__ T = &g_t[0];
    float* __restrict__ Out = OutExt ? OutExt : &g_h[osel][0];

    const int node = blockIdx.x;
    const int tid  = threadIdx.x;

    __shared__ int   s_src[NT];
    __shared__ float s_w[NT];

    float di = g_dinv[node];
    float w0 = di * di;
    float4 v = ((const float4*)(T + (size_t)node * C))[tid];
    float4 acc = make_float4(v.x * w0, v.y * w0, v.z * w0, v.w * w0);

    int beg = g_rowstart[node];
    int end = g_rowstart[node + 1];

    for (int j0 = beg; j0 < end; j0 += NT) {
        int n = min(NT, end - j0);
        __syncthreads();
        if (tid < n) {
            s_src[tid] = g_csr_src[j0 + tid];
            s_w[tid]   = g_csr_w[j0 + tid];
        }
        __syncthreads();
        for (int j = 0; j < n; j++) {
            int   s = s_src[j];
            float w = s_w[j];
            float4 hv = ((const float4*)(T + (size_t)s * C))[tid];
            acc.x = fmaf(w, hv.x, acc.x);
            acc.y = fmaf(w, hv.y, acc.y);
            acc.z = fmaf(w, hv.z, acc.z);
            acc.w = fmaf(w, hv.w, acc.w);
        }
    }

    float4 b4 = ((const float4*)bias)[tid];
    acc.x += b4.x; acc.y += b4.y; acc.z += b4.z; acc.w += b4.w;
    if (RELU) {
        acc.x = fmaxf(acc.x, 0.f); acc.y = fmaxf(acc.y, 0.f);
        acc.z = fmaxf(acc.z, 0.f); acc.w = fmaxf(acc.w, 0.f);
    }
    if (RES) {
        const float* __restrict__ Hres = &g_h[rsel][0];
        float4 r4 = ((const float4*)(Hres + (size_t)node * C))[tid];
        acc.x += r4.x; acc.y += r4.y; acc.z += r4.z; acc.w += r4.w;
    }
    ((float4*)(Out + (size_t)node * C))[tid] = acc;
}

// ---------------- launch ----------------
extern "C" void kernel_launch(void* const* d_in, const int* in_sizes, int n_in,
                              void* d_out, int out_size) {
    const float* x  = (const float*)d_in[0];
    const int*   ei = (const int*)d_in[1];     // int32 view; layout probed on device
    const float* W1 = (const float*)d_in[2];
    const float* b1 = (const float*)d_in[3];
    const float* Wr = (const float*)d_in[4];
    const float* br = (const float*)d_in[5];
    const float* Wx = (const float*)d_in[6];
    const float* bx = (const float*)d_in[7];
    float* out = (float*)d_out;

    // ---- build normalized adjacency (CSR) once ----
    k_detect <<<1, 256>>>(ei);
    k_zero   <<<(NN + 255) / 256, 256>>>();
    k_count  <<<(NE + 255) / 256, 256>>>(ei);
    k_dinv   <<<(NN + 255) / 256, 256>>>();
    k_scan   <<<1, 1024>>>();
    k_scatter<<<(NE + 255) / 256, 256>>>(ei);

    dim3 gemmGrid512(C_H / 128, (NN + 127) / 128);
    dim3 gemmGrid256(C_OUT / 128, (NN + 127) / 128);

    // layer 0: h0 = relu(A (x@W1) + b1)   -> g_h[0]
    k_sgemm<<<gemmGrid512, 256>>>(x, -1, W1, NN, C_H, C_IN);
    k_spmm<C_H, true, false><<<NN, C_H / 4>>>(b1, 0, nullptr, 0);

    // 4 residual layers: h = relu(A (h@Wr) + br) + h   (ping-pong g_h[0]/g_h[1])
    int cur = 0;
    for (int l = 0; l < 4; l++) {
        int nxt = cur ^ 1;
        k_sgemm<<<gemmGrid512, 256>>>(nullptr, cur, Wr, NN, C_H, C_H);
        k_spmm<C_H, true, true><<<NN, C_H / 4>>>(br, cur, nullptr, nxt);
        cur = nxt;
    }

    // final: out = A (h@Wx) + bx
    k_sgemm<<<gemmGrid256, 256>>>(nullptr, cur, Wx, NN, C_OUT, C_H);
    k_spmm<C_OUT, false, false><<<NN, C_OUT / 4>>>(bx, 0, out, 0);
}

// round 5
// speedup vs baseline: 1.6082x; 1.6082x over previous
#include <cuda_runtime.h>
#include <cuda_bf16.h>
#include <cstddef>
#include <cstdint>

#define NN 50000
#define NE 800000
#define C_IN 512
#define C_H 512
#define C_OUT 256

// ---------------- scratch (static device memory; no allocations) ----------------
__device__ int   g_is64;                 // 1 if edge_index buffer is int64-laid-out
__device__ int   g_cnt[NN];
__device__ int   g_cursor[NN];
__device__ float g_dinv[NN];
__device__ int   g_rowstart[NN + 1];
__device__ int   g_csr_src[NE];
__device__ float g_csr_w[NE];
__device__ float g_t[(size_t)NN * C_H];          // GEMM output buffer (t = h @ W)
__device__ float g_h[2][(size_t)NN * C_H];       // ping/pong hidden state

// read edge endpoint robustly under either dtype layout
__device__ __forceinline__ int edge_src(const int* ei, int e, int is64) {
    return is64 ? ei[2 * e] : ei[e];
}
__device__ __forceinline__ int edge_dst(const int* ei, int e, int is64) {
    return is64 ? ei[2 * (NE + e)] : ei[NE + e];
}

// ---------------- dtype-layout probe ----------------
__global__ void k_detect(const int* __restrict__ ei) {
    __shared__ int s_or[256];
    int acc = 0;
    for (int i = threadIdx.x; i < 4096; i += 256) acc |= ei[2 * i + 1];
    s_or[threadIdx.x] = acc;
    __syncthreads();
    for (int off = 128; off > 0; off >>= 1) {
        if (threadIdx.x < off) s_or[threadIdx.x] |= s_or[threadIdx.x + off];
        __syncthreads();
    }
    if (threadIdx.x == 0) g_is64 = (s_or[0] == 0) ? 1 : 0;
}

// ---------------- graph preprocessing ----------------
__global__ void k_zero() {
    int i = blockIdx.x * blockDim.x + threadIdx.x;
    if (i < NN) { g_cnt[i] = 0; g_cursor[i] = 0; }
}

__global__ void k_count(const int* __restrict__ ei) {
    int e = blockIdx.x * blockDim.x + threadIdx.x;
    if (e < NE) {
        int d = edge_dst(ei, e, g_is64);
        if ((unsigned)d < NN) atomicAdd(&g_cnt[d], 1);
    }
}

__global__ void k_dinv() {
    int i = blockIdx.x * blockDim.x + threadIdx.x;
    if (i < NN) {
        float deg = (float)(g_cnt[i] + 1);   // +1 self loop
        g_dinv[i] = rsqrtf(deg);
    }
}

// single-block exclusive scan of g_cnt -> g_rowstart
__global__ void k_scan() {
    __shared__ int s[1024];
    int carry = 0;
    for (int base = 0; base < NN; base += 1024) {
        int i = base + (int)threadIdx.x;
        int v = (i < NN) ? g_cnt[i] : 0;
        s[threadIdx.x] = v;
        __syncthreads();
        #pragma unroll
        for (int off = 1; off < 1024; off <<= 1) {
            int t = (threadIdx.x >= (unsigned)off) ? s[threadIdx.x - off] : 0;
            __syncthreads();
            s[threadIdx.x] += t;
            __syncthreads();
        }
        if (i < NN) g_rowstart[i] = carry + s[threadIdx.x] - v;  // exclusive
        carry += s[1023];
        __syncthreads();
    }
    if (threadIdx.x == 0) g_rowstart[NN] = carry;
}

__global__ void k_scatter(const int* __restrict__ ei) {
    int e = blockIdx.x * blockDim.x + threadIdx.x;
    if (e < NE) {
        int is64 = g_is64;
        int s = edge_src(ei, e, is64);
        int d = edge_dst(ei, e, is64);
        if ((unsigned)s < NN && (unsigned)d < NN) {
            int pos = g_rowstart[d] + atomicAdd(&g_cursor[d], 1);
            g_csr_src[pos] = s;
            g_csr_w[pos]   = g_dinv[s] * g_dinv[d];
        }
    }
}

// ---------------- tensor-core GEMM (bf16 3-split, fp32-accurate) ----------------
// g_t[M,N] = A[M,K] @ B[K,N];  A = (asel>=0) ? g_h[asel] : Aext.
// A,B row-major fp32. Split x = hi + lo (bf16 each); D = Ah*Bh + Ah*Bl + Al*Bh.
// Block tile 128x128x32, 8 warps (warp tile 32x64), mma.sync.m16n8k16.

#define BM 128
#define BN 128
#define BK 32
#define AS_STRIDE 40    // 32 + 8 pad (bf16 elems)
#define BS_STRIDE 136   // 128 + 8 pad

__device__ __forceinline__ uint32_t smem_u32(const void* p) {
    return (uint32_t)__cvta_generic_to_shared(p);
}

__device__ __forceinline__ void ldsm_x4(uint32_t& r0, uint32_t& r1,
                                        uint32_t& r2, uint32_t& r3, uint32_t addr) {
    asm volatile("ldmatrix.sync.aligned.m8n8.x4.shared.b16 {%0,%1,%2,%3}, [%4];"
                 : "=r"(r0), "=r"(r1), "=r"(r2), "=r"(r3) : "r"(addr));
}

__device__ __forceinline__ void ldsm_x4_t(uint32_t& r0, uint32_t& r1,
                                          uint32_t& r2, uint32_t& r3, uint32_t addr) {
    asm volatile("ldmatrix.sync.aligned.m8n8.x4.trans.shared.b16 {%0,%1,%2,%3}, [%4];"
                 : "=r"(r0), "=r"(r1), "=r"(r2), "=r"(r3) : "r"(addr));
}

__device__ __forceinline__ void mma16816(float* d, const uint32_t* a, const uint32_t* b) {
    asm volatile(
        "mma.sync.aligned.m16n8k16.row.col.f32.bf16.bf16.f32 "
        "{%0,%1,%2,%3}, {%4,%5,%6,%7}, {%8,%9}, {%0,%1,%2,%3};"
        : "+f"(d[0]), "+f"(d[1]), "+f"(d[2]), "+f"(d[3])
        : "r"(a[0]), "r"(a[1]), "r"(a[2]), "r"(a[3]), "r"(b[0]), "r"(b[1]));
}

__device__ __forceinline__ uint32_t pack_bf16x2(float f0, float f1) {
    __nv_bfloat162 v = __floats2bfloat162_rn(f0, f1);
    return *(uint32_t*)&v;
}

__global__ __launch_bounds__(256)
void k_gemm_tc(const float* __restrict__ Aext, int asel,
               const float* __restrict__ B, int M, int N, int K) {
    const float* __restrict__ A = (asel >= 0) ? &g_h[asel][0] : Aext;
    float* __restrict__ C = &g_t[0];

    // [plane][row][col]: plane 0 = hi, 1 = lo
    __shared__ __nv_bfloat16 As[2][BM][AS_STRIDE];
    __shared__ __nv_bfloat16 Bs[2][BK][BS_STRIDE];

    const int tid  = threadIdx.x;
    const int wid  = tid >> 5;
    const int lane = tid & 31;
    const int warp_m = wid >> 1;          // 0..3 -> m offset 32*warp_m
    const int warp_n = wid & 1;           // 0..1 -> n offset 64*warp_n

    const int mBase = blockIdx.y * BM;
    const int nBase = blockIdx.x * BN;

    float acc[2][8][4];
    #pragma unroll
    for (int i = 0; i < 2; i++)
        #pragma unroll
        for (int j = 0; j < 8; j++)
            #pragma unroll
            for (int c = 0; c < 4; c++) acc[i][j][c] = 0.0f;

    // A staging: 128 rows x 32 cols, thread loads 4x float4
    const int aRow0 = tid >> 3;            // 0..31
    const int aCol  = (tid & 7) * 4;       // 0..28
    // B staging: 32 rows x 128 cols
    const int bRow0 = tid >> 5;            // 0..7
    const int bCol  = (tid & 31) * 4;      // 0..124

    for (int k0 = 0; k0 < K; k0 += BK) {
        // ---- stage A (convert fp32 -> hi/lo bf16) ----
        #pragma unroll
        for (int i = 0; i < 4; i++) {
            int row = aRow0 + i * 32;
            int mRow = mBase + row;
            float4 v = (mRow < M) ? *(const float4*)(A + (size_t)mRow * K + k0 + aCol)
                                  : make_float4(0.f, 0.f, 0.f, 0.f);
            float h0 = __bfloat162float(__float2bfloat16_rn(v.x));
            float h1 = __bfloat162float(__float2bfloat16_rn(v.y));
            float h2 = __bfloat162float(__float2bfloat16_rn(v.z));
            float h3 = __bfloat162float(__float2bfloat16_rn(v.w));
            uint32_t* ph = (uint32_t*)&As[0][row][aCol];
            uint32_t* pl = (uint32_t*)&As[1][row][aCol];
            ph[0] = pack_bf16x2(v.x, v.y);
            ph[1] = pack_bf16x2(v.z, v.w);
            pl[0] = pack_bf16x2(v.x - h0, v.y - h1);
            pl[1] = pack_bf16x2(v.z - h2, v.w - h3);
        }
        // ---- stage B ----
        #pragma unroll
        for (int i = 0; i < 4; i++) {
            int row = bRow0 + i * 8;
            float4 v = *(const float4*)(B + (size_t)(k0 + row) * N + nBase + bCol);
            float h0 = __bfloat162float(__float2bfloat16_rn(v.x));
            float h1 = __bfloat162float(__float2bfloat16_rn(v.y));
            float h2 = __bfloat162float(__float2bfloat16_rn(v.z));
            float h3 = __bfloat162float(__float2bfloat16_rn(v.w));
            uint32_t* ph = (uint32_t*)&Bs[0][row][bCol];
            uint32_t* pl = (uint32_t*)&Bs[1][row][bCol];
            ph[0] = pack_bf16x2(v.x, v.y);
            ph[1] = pack_bf16x2(v.z, v.w);
            pl[0] = pack_bf16x2(v.x - h0, v.y - h1);
            pl[1] = pack_bf16x2(v.z - h2, v.w - h3);
        }
        __syncthreads();

        #pragma unroll
        for (int ks = 0; ks < BK; ks += 16) {
            // load A frags (2 m-frags x 4 regs, hi+lo)
            uint32_t ah[2][4], al[2][4];
            #pragma unroll
            for (int mf = 0; mf < 2; mf++) {
                int r = warp_m * 32 + mf * 16 + (lane & 15);
                int c = ks + (lane >> 4) * 8;
                ldsm_x4(ah[mf][0], ah[mf][1], ah[mf][2], ah[mf][3],
                        smem_u32(&As[0][r][c]));
                ldsm_x4(al[mf][0], al[mf][1], al[mf][2], al[mf][3],
                        smem_u32(&As[1][r][c]));
            }
            // load B frags (8 n-frags as 4 pairs, hi+lo)
            uint32_t bh[4][4], bl[4][4];
            #pragma unroll
            for (int p = 0; p < 4; p++) {
                int r = ks + (lane & 15);
                int c = warp_n * 64 + p * 16 + (lane >> 4) * 8;
                ldsm_x4_t(bh[p][0], bh[p][1], bh[p][2], bh[p][3],
                          smem_u32(&Bs[0][r][c]));
                ldsm_x4_t(bl[p][0], bl[p][1], bl[p][2], bl[p][3],
                          smem_u32(&Bs[1][r][c]));
            }
            // mma: hi*hi + hi*lo + lo*hi
            #pragma unroll
            for (int mf = 0; mf < 2; mf++) {
                #pragma unroll
                for (int nf = 0; nf < 8; nf++) {
                    const uint32_t* bhp = &bh[nf >> 1][(nf & 1) * 2];
                    const uint32_t* blp = &bl[nf >> 1][(nf & 1) * 2];
                    mma16816(acc[mf][nf], ah[mf], bhp);
                    mma16816(acc[mf][nf], ah[mf], blp);
                    mma16816(acc[mf][nf], al[mf], bhp);
                }
            }
        }
        __syncthreads();
    }

    // ---- store C ----
    const int group = lane >> 2;          // 0..7
    const int col2  = (lane & 3) * 2;
    #pragma unroll
    for (int mf = 0; mf < 2; mf++) {
        int r0 = mBase + warp_m * 32 + mf * 16 + group;
        #pragma unroll
        for (int nf = 0; nf < 8; nf++) {
            int cidx = nBase + warp_n * 64 + nf * 8 + col2;
            if (r0 < M)
                *(float2*)(C + (size_t)r0 * N + cidx) = make_float2(acc[mf][nf][0], acc[mf][nf][1]);
            if (r0 + 8 < M)
                *(float2*)(C + (size_t)(r0 + 8) * N + cidx) = make_float2(acc[mf][nf][2], acc[mf][nf][3]);
        }
    }
}

// ---------------- SpMM ----------------
// out[d] = relu?( sum_e w_e * t[src_e] + dinv[d]^2 * t[d] + bias ) (+ residual g_h[rsel])
template <int C, bool RELU, bool RES>
__global__ void k_spmm(const float* __restrict__ bias,
                       int rsel, float* __restrict__ OutExt, int osel) {
    constexpr int NT = C / 4;
    const float* __restrict__ T = &g_t[0];
    float* __restrict__ Out = OutExt ? OutExt : &g_h[osel][0];

    const int node = blockIdx.x;
    const int tid  = threadIdx.x;

    __shared__ int   s_src[NT];
    __shared__ float s_w[NT];

    float di = g_dinv[node];
    float w0 = di * di;
    float4 v = ((const float4*)(T + (size_t)node * C))[tid];
    float4 acc = make_float4(v.x * w0, v.y * w0, v.z * w0, v.w * w0);

    int beg = g_rowstart[node];
    int end = g_rowstart[node + 1];

    for (int j0 = beg; j0 < end; j0 += NT) {
        int n = min(NT, end - j0);
        __syncthreads();
        if (tid < n) {
            s_src[tid] = g_csr_src[j0 + tid];
            s_w[tid]   = g_csr_w[j0 + tid];
        }
        __syncthreads();
        for (int j = 0; j < n; j++) {
            int   s = s_src[j];
            float w = s_w[j];
            float4 hv = ((const float4*)(T + (size_t)s * C))[tid];
            acc.x = fmaf(w, hv.x, acc.x);
            acc.y = fmaf(w, hv.y, acc.y);
            acc.z = fmaf(w, hv.z, acc.z);
            acc.w = fmaf(w, hv.w, acc.w);
        }
    }

    float4 b4 = ((const float4*)bias)[tid];
    acc.x += b4.x; acc.y += b4.y; acc.z += b4.z; acc.w += b4.w;
    if (RELU) {
        acc.x = fmaxf(acc.x, 0.f); acc.y = fmaxf(acc.y, 0.f);
        acc.z = fmaxf(acc.z, 0.f); acc.w = fmaxf(acc.w, 0.f);
    }
    if (RES) {
        const float* __restrict__ Hres = &g_h[rsel][0];
        float4 r4 = ((const float4*)(Hres + (size_t)node * C))[tid];
        acc.x += r4.x; acc.y += r4.y; acc.z += r4.z; acc.w += r4.w;
    }
    ((float4*)(Out + (size_t)node * C))[tid] = acc;
}

// ---------------- launch ----------------
extern "C" void kernel_launch(void* const* d_in, const int* in_sizes, int n_in,
                              void* d_out, int out_size) {
    const float* x  = (const float*)d_in[0];
    const int*   ei = (const int*)d_in[1];     // int32 view; layout probed on device
    const float* W1 = (const float*)d_in[2];
    const float* b1 = (const float*)d_in[3];
    const float* Wr = (const float*)d_in[4];
    const float* br = (const float*)d_in[5];
    const float* Wx = (const float*)d_in[6];
    const float* bx = (const float*)d_in[7];
    float* out = (float*)d_out;

    // ---- build normalized adjacency (CSR) once ----
    k_detect <<<1, 256>>>(ei);
    k_zero   <<<(NN + 255) / 256, 256>>>();
    k_count  <<<(NE + 255) / 256, 256>>>(ei);
    k_dinv   <<<(NN + 255) / 256, 256>>>();
    k_scan   <<<1, 1024>>>();
    k_scatter<<<(NE + 255) / 256, 256>>>(ei);

    dim3 gemmGrid512(C_H / BN, (NN + BM - 1) / BM);
    dim3 gemmGrid256(C_OUT / BN, (NN + BM - 1) / BM);

    // layer 0: h0 = relu(A (x@W1) + b1)   -> g_h[0]
    k_gemm_tc<<<gemmGrid512, 256>>>(x, -1, W1, NN, C_H, C_IN);
    k_spmm<C_H, true, false><<<NN, C_H / 4>>>(b1, 0, nullptr, 0);

    // 4 residual layers: h = relu(A (h@Wr) + br) + h   (ping-pong g_h[0]/g_h[1])
    int cur = 0;
    for (int l = 0; l < 4; l++) {
        int nxt = cur ^ 1;
        k_gemm_tc<<<gemmGrid512, 256>>>(nullptr, cur, Wr, NN, C_H, C_H);
        k_spmm<C_H, true, true><<<NN, C_H / 4>>>(br, cur, nullptr, nxt);
        cur = nxt;
    }

    // final: out = A (h@Wx) + bx
    k_gemm_tc<<<gemmGrid256, 256>>>(nullptr, cur, Wx, NN, C_OUT, C_H);
    k_spmm<C_OUT, false, false><<<NN, C_OUT / 4>>>(bx, 0, out, 0);
}

// round 8
// speedup vs baseline: 1.9907x; 1.2378x over previous
#include <cuda_runtime.h>
#include <cuda_bf16.h>
#include <cstddef>
#include <cstdint>

#define NN 50000
#define NE 800000
#define C_IN 512
#define C_H 512
#define C_OUT 256
#define KDIM 512

// ---------------- scratch (static device memory; no allocations) ----------------
__device__ int   g_is64;
__device__ int   g_cnt[NN];
__device__ int   g_cursor[NN];
__device__ float g_dinv[NN];
__device__ int   g_rowstart[NN + 1];
__device__ int   g_csr_src[NE];
__device__ float g_csr_w[NE];
__device__ float g_t[(size_t)NN * C_H];                      // GEMM output (fp32)
__device__ __nv_bfloat16 g_sa[3][2][(size_t)NN * C_H];       // split A operands [sel][hi/lo]
__device__ __nv_bfloat16 g_w[3][2][(size_t)KDIM * C_H];      // split weights [wsel][hi/lo][K][N]

// ---------------- helpers ----------------
__device__ __forceinline__ uint32_t smem_u32(const void* p) {
    return (uint32_t)__cvta_generic_to_shared(p);
}
__device__ __forceinline__ void cp16(uint32_t dst, const void* src, bool valid) {
    int sz = valid ? 16 : 0;
    asm volatile("cp.async.cg.shared.global [%0], [%1], 16, %2;"
                 :: "r"(dst), "l"(src), "r"(sz) : "memory");
}
__device__ __forceinline__ void cp_commit() {
    asm volatile("cp.async.commit_group;" ::: "memory");
}
template <int N> __device__ __forceinline__ void cp_wait() {
    asm volatile("cp.async.wait_group %0;" :: "n"(N) : "memory");
}
__device__ __forceinline__ void ldsm_x4(uint32_t& r0, uint32_t& r1,
                                        uint32_t& r2, uint32_t& r3, uint32_t addr) {
    asm volatile("ldmatrix.sync.aligned.m8n8.x4.shared.b16 {%0,%1,%2,%3}, [%4];"
                 : "=r"(r0), "=r"(r1), "=r"(r2), "=r"(r3) : "r"(addr));
}
__device__ __forceinline__ void ldsm_x4_t(uint32_t& r0, uint32_t& r1,
                                          uint32_t& r2, uint32_t& r3, uint32_t addr) {
    asm volatile("ldmatrix.sync.aligned.m8n8.x4.trans.shared.b16 {%0,%1,%2,%3}, [%4];"
                 : "=r"(r0), "=r"(r1), "=r"(r2), "=r"(r3) : "r"(addr));
}
__device__ __forceinline__ void mma16816(float* d, const uint32_t* a, const uint32_t* b) {
    asm volatile(
        "mma.sync.aligned.m16n8k16.row.col.f32.bf16.bf16.f32 "
        "{%0,%1,%2,%3}, {%4,%5,%6,%7}, {%8,%9}, {%0,%1,%2,%3};"
        : "+f"(d[0]), "+f"(d[1]), "+f"(d[2]), "+f"(d[3])
        : "r"(a[0]), "r"(a[1]), "r"(a[2]), "r"(a[3]), "r"(b[0]), "r"(b[1]));
}

// ---------------- edge helpers / preprocessing ----------------
__device__ __forceinline__ int edge_src(const int* ei, int e, int is64) {
    return is64 ? ei[2 * e] : ei[e];
}
__device__ __forceinline__ int edge_dst(const int* ei, int e, int is64) {
    return is64 ? ei[2 * (NE + e)] : ei[NE + e];
}

__global__ void k_detect(const int* __restrict__ ei) {
    __shared__ int s_or[256];
    int acc = 0;
    for (int i = threadIdx.x; i < 4096; i += 256) acc |= ei[2 * i + 1];
    s_or[threadIdx.x] = acc;
    __syncthreads();
    for (int off = 128; off > 0; off >>= 1) {
        if (threadIdx.x < off) s_or[threadIdx.x] |= s_or[threadIdx.x + off];
        __syncthreads();
    }
    if (threadIdx.x == 0) g_is64 = (s_or[0] == 0) ? 1 : 0;
}

__global__ void k_zero() {
    int i = blockIdx.x * blockDim.x + threadIdx.x;
    if (i < NN) { g_cnt[i] = 0; g_cursor[i] = 0; }
}

__global__ void k_count(const int* __restrict__ ei) {
    int e = blockIdx.x * blockDim.x + threadIdx.x;
    if (e < NE) {
        int d = edge_dst(ei, e, g_is64);
        if ((unsigned)d < NN) atomicAdd(&g_cnt[d], 1);
    }
}

__global__ void k_dinv() {
    int i = blockIdx.x * blockDim.x + threadIdx.x;
    if (i < NN) g_dinv[i] = rsqrtf((float)(g_cnt[i] + 1));
}

__global__ void k_scan() {
    __shared__ int s[1024];
    int carry = 0;
    for (int base = 0; base < NN; base += 1024) {
        int i = base + (int)threadIdx.x;
        int v = (i < NN) ? g_cnt[i] : 0;
        s[threadIdx.x] = v;
        __syncthreads();
        #pragma unroll
        for (int off = 1; off < 1024; off <<= 1) {
            int t = (threadIdx.x >= (unsigned)off) ? s[threadIdx.x - off] : 0;
            __syncthreads();
            s[threadIdx.x] += t;
            __syncthreads();
        }
        if (i < NN) g_rowstart[i] = carry + s[threadIdx.x] - v;
        carry += s[1023];
        __syncthreads();
    }
    if (threadIdx.x == 0) g_rowstart[NN] = carry;
}

__global__ void k_scatter(const int* __restrict__ ei) {
    int e = blockIdx.x * blockDim.x + threadIdx.x;
    if (e < NE) {
        int is64 = g_is64;
        int s = edge_src(ei, e, is64);
        int d = edge_dst(ei, e, is64);
        if ((unsigned)s < NN && (unsigned)d < NN) {
            int pos = g_rowstart[d] + atomicAdd(&g_cursor[d], 1);
            g_csr_src[pos] = s;
            g_csr_w[pos]   = g_dinv[s] * g_dinv[d];
        }
    }
}

// ---------------- split conversions ----------------
__global__ void k_split_x(const float* __restrict__ x) {
    size_t i = (size_t)blockIdx.x * blockDim.x + threadIdx.x;
    if (i < (size_t)NN * C_H) {
        float v = x[i];
        __nv_bfloat16 h = __float2bfloat16_rn(v);
        g_sa[2][0][i] = h;
        g_sa[2][1][i] = __float2bfloat16_rn(v - __bfloat162float(h));
    }
}

// W [K][N] fp32 -> g_w[wsel] planes, same [K][N] layout
__global__ void k_split_w(const float* __restrict__ W, int wsel, int N) {
    int i = blockIdx.x * blockDim.x + threadIdx.x;
    if (i < KDIM * N) {
        float v = W[i];
        __nv_bfloat16 h = __float2bfloat16_rn(v);
        g_w[wsel][0][i] = h;
        g_w[wsel][1][i] = __float2bfloat16_rn(v - __bfloat162float(h));
    }
}

// ---------------- tensor-core GEMM (bf16 3-split, cp.async pipelined) ----------------
// g_t[0:M, 0:Ng] = (g_sa[asel].hi + .lo) @ (g_w[wsel].hi + .lo), 3-product scheme.
// Block 128x128x32, 8 warps (32x64 each), mma.sync.m16n8k16, 2-stage cp.async.

#define A_STRIDE_B 144            // bytes per A smem row (64B data + pad; %16==0, %128==16)
#define B_STRIDE_B 272            // bytes per B smem row (256B data + pad)
#define A_PLANE_SZ (128 * A_STRIDE_B)        // 18432
#define B_PLANE_SZ (32 * B_STRIDE_B)         // 8704
#define OFF_B_TILE (2 * A_PLANE_SZ)          // 36864
#define BUF_SZ (2 * A_PLANE_SZ + 2 * B_PLANE_SZ)   // 54272
#define GEMM_SMEM (2 * BUF_SZ)               // 108544

__global__ void __launch_bounds__(256)
k_gemm_tc(int asel, int wsel, int M, int Ng) {
    extern __shared__ char smem[];
    const uint32_t sb = smem_u32(smem);

    const int tid  = threadIdx.x;
    const int wid  = tid >> 5;
    const int lane = tid & 31;
    const int warp_m = wid >> 1;
    const int warp_n = wid & 1;

    const int mBase = blockIdx.y * 128;
    const int nBase = blockIdx.x * 128;

    const __nv_bfloat16* __restrict__ Ah = &g_sa[asel][0][0];
    const __nv_bfloat16* __restrict__ Al = &g_sa[asel][1][0];
    const __nv_bfloat16* __restrict__ Bh = &g_w[wsel][0][0];
    const __nv_bfloat16* __restrict__ Bl = &g_w[wsel][1][0];

    float acc[2][8][4];
    #pragma unroll
    for (int i = 0; i < 2; i++)
        #pragma unroll
        for (int j = 0; j < 8; j++)
            #pragma unroll
            for (int c = 0; c < 4; c++) acc[i][j][c] = 0.0f;

    // stage one K-chunk (32 cols) into buffer b
    auto stage = [&](int c, int b) {
        const int k0 = c * 32;
        const uint32_t bb = sb + b * BUF_SZ;
        #pragma unroll
        for (int q = 0; q < 2; q++) {
            int ch = tid * 2 + q;              // 0..511
            int r = ch >> 2, cc = ch & 3;      // A: 128 rows x 4 chunks
            int gm = mBase + r;
            bool ok = gm < M;
            size_t go = (size_t)(ok ? gm : 0) * KDIM + k0 + cc * 8;
            uint32_t so = bb + r * A_STRIDE_B + cc * 16;
            cp16(so, Ah + go, ok);
            cp16(so + A_PLANE_SZ, Al + go, ok);
        }
        #pragma unroll
        for (int q = 0; q < 2; q++) {
            int ch = tid * 2 + q;
            int r = ch >> 4, cc = ch & 15;     // B: 32 rows x 16 chunks
            size_t go = (size_t)(k0 + r) * Ng + nBase + cc * 8;
            uint32_t so = bb + OFF_B_TILE + r * B_STRIDE_B + cc * 16;
            cp16(so, Bh + go, true);
            cp16(so + B_PLANE_SZ, Bl + go, true);
        }
        cp_commit();
    };

    stage(0, 0);

    const int NITER = KDIM / 32;               // 16
    for (int c = 0; c < NITER; c++) {
        if (c + 1 < NITER) {
            stage(c + 1, (c + 1) & 1);
            cp_wait<1>();
        } else {
            cp_wait<0>();
        }
        __syncthreads();

        const uint32_t bb = sb + (c & 1) * BUF_SZ;
        #pragma unroll
        for (int ks = 0; ks < 32; ks += 16) {
            uint32_t ah[2][4], al[2][4];
            #pragma unroll
            for (int mf = 0; mf < 2; mf++) {
                int r = warp_m * 32 + mf * 16 + (lane & 15);
                int cbytes = (ks + (lane >> 4) * 8) * 2;
                uint32_t addr = bb + r * A_STRIDE_B + cbytes;
                ldsm_x4(ah[mf][0], ah[mf][1], ah[mf][2], ah[mf][3], addr);
                ldsm_x4(al[mf][0], al[mf][1], al[mf][2], al[mf][3], addr + A_PLANE_SZ);
            }
            uint32_t bh[4][4], bl[4][4];
            #pragma unroll
            for (int p = 0; p < 4; p++) {
                int r = ks + (lane & 15);
                int cbytes = (warp_n * 64 + p * 16 + (lane >> 4) * 8) * 2;
                uint32_t addr = bb + OFF_B_TILE + r * B_STRIDE_B + cbytes;
                ldsm_x4_t(bh[p][0], bh[p][1], bh[p][2], bh[p][3], addr);
                ldsm_x4_t(bl[p][0], bl[p][1], bl[p][2], bl[p][3], addr + B_PLANE_SZ);
            }
            #pragma unroll
            for (int mf = 0; mf < 2; mf++) {
                #pragma unroll
                for (int nf = 0; nf < 8; nf++) {
                    const uint32_t* bhp = &bh[nf >> 1][(nf & 1) * 2];
                    const uint32_t* blp = &bl[nf >> 1][(nf & 1) * 2];
                    mma16816(acc[mf][nf], ah[mf], bhp);
                    mma16816(acc[mf][nf], ah[mf], blp);
                    mma16816(acc[mf][nf], al[mf], bhp);
                }
            }
        }
        __syncthreads();
    }

    // ---- store C (fp32) ----
    float* __restrict__ C = &g_t[0];
    const int group = lane >> 2;
    const int col2  = (lane & 3) * 2;
    #pragma unroll
    for (int mf = 0; mf < 2; mf++) {
        int r0 = mBase + warp_m * 32 + mf * 16 + group;
        #pragma unroll
        for (int nf = 0; nf < 8; nf++) {
            int cidx = nBase + warp_n * 64 + nf * 8 + col2;
            if (r0 < M)
                *(float2*)(C + (size_t)r0 * Ng + cidx) = make_float2(acc[mf][nf][0], acc[mf][nf][1]);
            if (r0 + 8 < M)
                *(float2*)(C + (size_t)(r0 + 8) * Ng + cidx) = make_float2(acc[mf][nf][2], acc[mf][nf][3]);
        }
    }
}

// ---------------- SpMM (hidden layers): writes split bf16 planes ----------------
template <bool RES>
__global__ void k_spmm_split(const float* __restrict__ bias, int rsel, int osel) {
    constexpr int NT = C_H / 4;                  // 128 threads
    const float* __restrict__ T = &g_t[0];

    const int node = blockIdx.x;
    const int tid  = threadIdx.x;

    __shared__ int   s_src[NT];
    __shared__ float s_w[NT];

    float di = g_dinv[node];
    float w0 = di * di;
    float4 v = ((const float4*)(T + (size_t)node * C_H))[tid];
    float4 acc = make_float4(v.x * w0, v.y * w0, v.z * w0, v.w * w0);

    int beg = g_rowstart[node];
    int end = g_rowstart[node + 1];

    for (int j0 = beg; j0 < end; j0 += NT) {
        int n = min(NT, end - j0);
        __syncthreads();
        if (tid < n) {
            s_src[tid] = g_csr_src[j0 + tid];
            s_w[tid]   = g_csr_w[j0 + tid];
        }
        __syncthreads();
        for (int j = 0; j < n; j++) {
            int   s = s_src[j];
            float w = s_w[j];
            float4 hv = ((const float4*)(T + (size_t)s * C_H))[tid];
            acc.x = fmaf(w, hv.x, acc.x);
            acc.y = fmaf(w, hv.y, acc.y);
            acc.z = fmaf(w, hv.z, acc.z);
            acc.w = fmaf(w, hv.w, acc.w);
        }
    }

    float4 b4 = ((const float4*)bias)[tid];
    acc.x += b4.x; acc.y += b4.y; acc.z += b4.z; acc.w += b4.w;
    acc.x = fmaxf(acc.x, 0.f); acc.y = fmaxf(acc.y, 0.f);
    acc.z = fmaxf(acc.z, 0.f); acc.w = fmaxf(acc.w, 0.f);

    size_t off = (size_t)node * C_H + tid * 4;
    if (RES) {
        const __nv_bfloat16* rh = &g_sa[rsel][0][0];
        const __nv_bfloat16* rl = &g_sa[rsel][1][0];
        acc.x += __bfloat162float(rh[off + 0]) + __bfloat162float(rl[off + 0]);
        acc.y += __bfloat162float(rh[off + 1]) + __bfloat162float(rl[off + 1]);
        acc.z += __bfloat162float(rh[off + 2]) + __bfloat162float(rl[off + 2]);
        acc.w += __bfloat162float(rh[off + 3]) + __bfloat162float(rl[off + 3]);
    }

    __nv_bfloat16 h0 = __float2bfloat16_rn(acc.x), h1 = __float2bfloat16_rn(acc.y);
    __nv_bfloat16 h2 = __float2bfloat16_rn(acc.z), h3 = __float2bfloat16_rn(acc.w);
    __nv_bfloat16 l0 = __float2bfloat16_rn(acc.x - __bfloat162float(h0));
    __nv_bfloat16 l1 = __float2bfloat16_rn(acc.y - __bfloat162float(h1));
    __nv_bfloat16 l2 = __float2bfloat16_rn(acc.z - __bfloat162float(h2));
    __nv_bfloat16 l3 = __float2bfloat16_rn(acc.w - __bfloat162float(h3));
    __nv_bfloat162 hp0 = {h0, h1}, hp1 = {h2, h3}, lp0 = {l0, l1}, lp1 = {l2, l3};
    *(uint2*)(&g_sa[osel][0][off]) = make_uint2(*(uint32_t*)&hp0, *(uint32_t*)&hp1);
    *(uint2*)(&g_sa[osel][1][off]) = make_uint2(*(uint32_t*)&lp0, *(uint32_t*)&lp1);
}

// ---------------- SpMM (final layer): fp32 external output ----------------
__global__ void k_spmm_out(const float* __restrict__ bias, float* __restrict__ Out) {
    constexpr int NT = C_OUT / 4;                // 64 threads
    const float* __restrict__ T = &g_t[0];

    const int node = blockIdx.x;
    const int tid  = threadIdx.x;

    __shared__ int   s_src[NT];
    __shared__ float s_w[NT];

    float di = g_dinv[node];
    float w0 = di * di;
    float4 v = ((const float4*)(T + (size_t)node * C_OUT))[tid];
    float4 acc = make_float4(v.x * w0, v.y * w0, v.z * w0, v.w * w0);

    int beg = g_rowstart[node];
    int end = g_rowstart[node + 1];

    for (int j0 = beg; j0 < end; j0 += NT) {
        int n = min(NT, end - j0);
        __syncthreads();
        if (tid < n) {
            s_src[tid] = g_csr_src[j0 + tid];
            s_w[tid]   = g_csr_w[j0 + tid];
        }
        __syncthreads();
        for (int j = 0; j < n; j++) {
            int   s = s_src[j];
            float w = s_w[j];
            float4 hv = ((const float4*)(T + (size_t)s * C_OUT))[tid];
            acc.x = fmaf(w, hv.x, acc.x);
            acc.y = fmaf(w, hv.y, acc.y);
            acc.z = fmaf(w, hv.z, acc.z);
            acc.w = fmaf(w, hv.w, acc.w);
        }
    }

    float4 b4 = ((const float4*)bias)[tid];
    acc.x += b4.x; acc.y += b4.y; acc.z += b4.z; acc.w += b4.w;
    ((float4*)(Out + (size_t)node * C_OUT))[tid] = acc;
}

// ---------------- launch ----------------
extern "C" void kernel_launch(void* const* d_in, const int* in_sizes, int n_in,
                              void* d_out, int out_size) {
    const float* x  = (const float*)d_in[0];
    const int*   ei = (const int*)d_in[1];
    const float* W1 = (const float*)d_in[2];
    const float* b1 = (const float*)d_in[3];
    const float* Wr = (const float*)d_in[4];
    const float* br = (const float*)d_in[5];
    const float* Wx = (const float*)d_in[6];
    const float* bx = (const float*)d_in[7];
    float* out = (float*)d_out;

    cudaFuncSetAttribute(k_gemm_tc, cudaFuncAttributeMaxDynamicSharedMemorySize,
                         GEMM_SMEM);

    // ---- CSR build ----
    k_detect <<<1, 256>>>(ei);
    k_zero   <<<(NN + 255) / 256, 256>>>();
    k_count  <<<(NE + 255) / 256, 256>>>(ei);
    k_dinv   <<<(NN + 255) / 256, 256>>>();
    k_scan   <<<1, 1024>>>();
    k_scatter<<<(NE + 255) / 256, 256>>>(ei);

    // ---- splits ----
    k_split_x<<<(int)(((size_t)NN * C_H + 255) / 256), 256>>>(x);
    k_split_w<<<(KDIM * C_H + 255) / 256, 256>>>(W1, 0, C_H);
    k_split_w<<<(KDIM * C_H + 255) / 256, 256>>>(Wr, 1, C_H);
    k_split_w<<<(KDIM * C_OUT + 255) / 256, 256>>>(Wx, 2, C_OUT);

    dim3 grid512(C_H / 128, (NN + 127) / 128);
    dim3 grid256(C_OUT / 128, (NN + 127) / 128);

    // layer 0: h0 = relu(A (x@W1) + b1) -> split sel 0
    k_gemm_tc<<<grid512, 256, GEMM_SMEM>>>(2, 0, NN, C_H);
    k_spmm_split<false><<<NN, C_H / 4>>>(b1, 0, 0);

    // 4 residual layers
    int cur = 0;
    for (int l = 0; l < 4; l++) {
        int nxt = cur ^ 1;
        k_gemm_tc<<<grid512, 256, GEMM_SMEM>>>(cur, 1, NN, C_H);
        k_spmm_split<true><<<NN, C_H / 4>>>(br, cur, nxt);
        cur = nxt;
    }

    // final
    k_gemm_tc<<<grid256, 256, GEMM_SMEM>>>(cur, 2, NN, C_OUT);
    k_spmm_out<<<NN, C_OUT / 4>>>(bx, out);
}

// round 9
// speedup vs baseline: 2.1880x; 1.0991x over previous
#include <cuda_runtime.h>
#include <cuda_bf16.h>
#include <cstddef>
#include <cstdint>

#define NN 50000
#define NE 800000
#define C_IN 512
#define C_H 512
#define C_OUT 256
#define KDIM 512
#define SCAN_NB 49            // ceil(50000/1024)

// ---------------- scratch (static device memory; no allocations) ----------------
__device__ int   g_is64;
__device__ int   g_cnt[NN];
__device__ int   g_cursor[NN];
__device__ float g_dinv[NN];
__device__ int   g_rowstart[NN + 1];
__device__ int   g_blocksum[SCAN_NB];
__device__ int   g_blockoff[SCAN_NB];
__device__ int   g_csr_src[NE];
__device__ float g_csr_w[NE];
__device__ float g_t[(size_t)NN * C_H];                      // GEMM output (fp32)
__device__ __nv_bfloat16 g_sa[3][2][(size_t)NN * C_H];       // split A operands [sel][hi/lo]
__device__ __nv_bfloat16 g_w[3][2][(size_t)KDIM * C_H];      // split weights [wsel][hi/lo][K][N]

// ---------------- helpers ----------------
__device__ __forceinline__ uint32_t smem_u32(const void* p) {
    return (uint32_t)__cvta_generic_to_shared(p);
}
__device__ __forceinline__ void cp16(uint32_t dst, const void* src, bool valid) {
    int sz = valid ? 16 : 0;
    asm volatile("cp.async.cg.shared.global [%0], [%1], 16, %2;"
                 :: "r"(dst), "l"(src), "r"(sz) : "memory");
}
__device__ __forceinline__ void cp_commit() {
    asm volatile("cp.async.commit_group;" ::: "memory");
}
template <int N> __device__ __forceinline__ void cp_wait() {
    asm volatile("cp.async.wait_group %0;" :: "n"(N) : "memory");
}
__device__ __forceinline__ void ldsm_x4(uint32_t& r0, uint32_t& r1,
                                        uint32_t& r2, uint32_t& r3, uint32_t addr) {
    asm volatile("ldmatrix.sync.aligned.m8n8.x4.shared.b16 {%0,%1,%2,%3}, [%4];"
                 : "=r"(r0), "=r"(r1), "=r"(r2), "=r"(r3) : "r"(addr));
}
__device__ __forceinline__ void ldsm_x4_t(uint32_t& r0, uint32_t& r1,
                                          uint32_t& r2, uint32_t& r3, uint32_t addr) {
    asm volatile("ldmatrix.sync.aligned.m8n8.x4.trans.shared.b16 {%0,%1,%2,%3}, [%4];"
                 : "=r"(r0), "=r"(r1), "=r"(r2), "=r"(r3) : "r"(addr));
}
__device__ __forceinline__ void mma16816(float* d, const uint32_t* a, const uint32_t* b) {
    asm volatile(
        "mma.sync.aligned.m16n8k16.row.col.f32.bf16.bf16.f32 "
        "{%0,%1,%2,%3}, {%4,%5,%6,%7}, {%8,%9}, {%0,%1,%2,%3};"
        : "+f"(d[0]), "+f"(d[1]), "+f"(d[2]), "+f"(d[3])
        : "r"(a[0]), "r"(a[1]), "r"(a[2]), "r"(a[3]), "r"(b[0]), "r"(b[1]));
}

// ---------------- edge helpers / preprocessing ----------------
__device__ __forceinline__ int edge_src(const int* ei, int e, int is64) {
    return is64 ? ei[2 * e] : ei[e];
}
__device__ __forceinline__ int edge_dst(const int* ei, int e, int is64) {
    return is64 ? ei[2 * (NE + e)] : ei[NE + e];
}

__global__ void k_detect(const int* __restrict__ ei) {
    __shared__ int s_or[256];
    int acc = 0;
    for (int i = threadIdx.x; i < 4096; i += 256) acc |= ei[2 * i + 1];
    s_or[threadIdx.x] = acc;
    __syncthreads();
    for (int off = 128; off > 0; off >>= 1) {
        if (threadIdx.x < off) s_or[threadIdx.x] |= s_or[threadIdx.x + off];
        __syncthreads();
    }
    if (threadIdx.x == 0) g_is64 = (s_or[0] == 0) ? 1 : 0;
}

__global__ void k_zero() {
    int i = blockIdx.x * blockDim.x + threadIdx.x;
    if (i < NN) { g_cnt[i] = 0; g_cursor[i] = 0; }
}

__global__ void k_count(const int* __restrict__ ei) {
    int e = blockIdx.x * blockDim.x + threadIdx.x;
    if (e < NE) {
        int d = edge_dst(ei, e, g_is64);
        if ((unsigned)d < NN) atomicAdd(&g_cnt[d], 1);
    }
}

__global__ void k_dinv() {
    int i = blockIdx.x * blockDim.x + threadIdx.x;
    if (i < NN) g_dinv[i] = rsqrtf((float)(g_cnt[i] + 1));
}

// ---- parallel scan: local (49 blocks x 1024) -> sums (1 block) -> add ----
__global__ void k_scan_local() {
    __shared__ int s[1024];
    int i = blockIdx.x * 1024 + threadIdx.x;
    int v = (i < NN) ? g_cnt[i] : 0;
    s[threadIdx.x] = v;
    __syncthreads();
    #pragma unroll
    for (int off = 1; off < 1024; off <<= 1) {
        int t = (threadIdx.x >= (unsigned)off) ? s[threadIdx.x - off] : 0;
        __syncthreads();
        s[threadIdx.x] += t;
        __syncthreads();
    }
    if (i < NN) g_rowstart[i] = s[threadIdx.x] - v;   // block-local exclusive
    if (threadIdx.x == 1023) g_blocksum[blockIdx.x] = s[1023];
}

__global__ void k_scan_sums() {
    __shared__ int s[64];
    int v = (threadIdx.x < SCAN_NB) ? g_blocksum[threadIdx.x] : 0;
    s[threadIdx.x] = v;
    __syncthreads();
    #pragma unroll
    for (int off = 1; off < 64; off <<= 1) {
        int t = (threadIdx.x >= (unsigned)off) ? s[threadIdx.x - off] : 0;
        __syncthreads();
        s[threadIdx.x] += t;
        __syncthreads();
    }
    if (threadIdx.x < SCAN_NB) g_blockoff[threadIdx.x] = s[threadIdx.x] - v;
    if (threadIdx.x == 63) g_rowstart[NN] = s[63];
}

__global__ void k_scan_add() {
    int i = blockIdx.x * 1024 + threadIdx.x;
    if (i < NN) g_rowstart[i] += g_blockoff[blockIdx.x];
}

__global__ void k_scatter(const int* __restrict__ ei) {
    int e = blockIdx.x * blockDim.x + threadIdx.x;
    if (e < NE) {
        int is64 = g_is64;
        int s = edge_src(ei, e, is64);
        int d = edge_dst(ei, e, is64);
        if ((unsigned)s < NN && (unsigned)d < NN) {
            int pos = g_rowstart[d] + atomicAdd(&g_cursor[d], 1);
            g_csr_src[pos] = s;
            g_csr_w[pos]   = g_dinv[s] * g_dinv[d];
        }
    }
}

// ---------------- split conversions ----------------
__global__ void k_split_x(const float* __restrict__ x) {
    size_t i = (size_t)blockIdx.x * blockDim.x + threadIdx.x;
    if (i < (size_t)NN * C_H) {
        float v = x[i];
        __nv_bfloat16 h = __float2bfloat16_rn(v);
        g_sa[2][0][i] = h;
        g_sa[2][1][i] = __float2bfloat16_rn(v - __bfloat162float(h));
    }
}

__global__ void k_split_w(const float* __restrict__ W, int wsel, int N) {
    int i = blockIdx.x * blockDim.x + threadIdx.x;
    if (i < KDIM * N) {
        float v = W[i];
        __nv_bfloat16 h = __float2bfloat16_rn(v);
        g_w[wsel][0][i] = h;
        g_w[wsel][1][i] = __float2bfloat16_rn(v - __bfloat162float(h));
    }
}

// ---------------- tensor-core GEMM (bf16 3-split, cp.async pipelined) ----------------
#define A_STRIDE_B 144
#define B_STRIDE_B 272
#define A_PLANE_SZ (128 * A_STRIDE_B)
#define B_PLANE_SZ (32 * B_STRIDE_B)
#define OFF_B_TILE (2 * A_PLANE_SZ)
#define BUF_SZ (2 * A_PLANE_SZ + 2 * B_PLANE_SZ)
#define GEMM_SMEM (2 * BUF_SZ)

__global__ void __launch_bounds__(256)
k_gemm_tc(int asel, int wsel, int M, int Ng) {
    extern __shared__ char smem[];
    const uint32_t sb = smem_u32(smem);

    const int tid  = threadIdx.x;
    const int wid  = tid >> 5;
    const int lane = tid & 31;
    const int warp_m = wid >> 1;
    const int warp_n = wid & 1;

    const int mBase = blockIdx.y * 128;
    const int nBase = blockIdx.x * 128;

    const __nv_bfloat16* __restrict__ Ah = &g_sa[asel][0][0];
    const __nv_bfloat16* __restrict__ Al = &g_sa[asel][1][0];
    const __nv_bfloat16* __restrict__ Bh = &g_w[wsel][0][0];
    const __nv_bfloat16* __restrict__ Bl = &g_w[wsel][1][0];

    float acc[2][8][4];
    #pragma unroll
    for (int i = 0; i < 2; i++)
        #pragma unroll
        for (int j = 0; j < 8; j++)
            #pragma unroll
            for (int c = 0; c < 4; c++) acc[i][j][c] = 0.0f;

    auto stage = [&](int c, int b) {
        const int k0 = c * 32;
        const uint32_t bb = sb + b * BUF_SZ;
        #pragma unroll
        for (int q = 0; q < 2; q++) {
            int ch = tid * 2 + q;
            int r = ch >> 2, cc = ch & 3;
            int gm = mBase + r;
            bool ok = gm < M;
            size_t go = (size_t)(ok ? gm : 0) * KDIM + k0 + cc * 8;
            uint32_t so = bb + r * A_STRIDE_B + cc * 16;
            cp16(so, Ah + go, ok);
            cp16(so + A_PLANE_SZ, Al + go, ok);
        }
        #pragma unroll
        for (int q = 0; q < 2; q++) {
            int ch = tid * 2 + q;
            int r = ch >> 4, cc = ch & 15;
            size_t go = (size_t)(k0 + r) * Ng + nBase + cc * 8;
            uint32_t so = bb + OFF_B_TILE + r * B_STRIDE_B + cc * 16;
            cp16(so, Bh + go, true);
            cp16(so + B_PLANE_SZ, Bl + go, true);
        }
        cp_commit();
    };

    stage(0, 0);

    const int NITER = KDIM / 32;
    for (int c = 0; c < NITER; c++) {
        if (c + 1 < NITER) {
            stage(c + 1, (c + 1) & 1);
            cp_wait<1>();
        } else {
            cp_wait<0>();
        }
        __syncthreads();

        const uint32_t bb = sb + (c & 1) * BUF_SZ;
        #pragma unroll
        for (int ks = 0; ks < 32; ks += 16) {
            uint32_t ah[2][4], al[2][4];
            #pragma unroll
            for (int mf = 0; mf < 2; mf++) {
                int r = warp_m * 32 + mf * 16 + (lane & 15);
                int cbytes = (ks + (lane >> 4) * 8) * 2;
                uint32_t addr = bb + r * A_STRIDE_B + cbytes;
                ldsm_x4(ah[mf][0], ah[mf][1], ah[mf][2], ah[mf][3], addr);
                ldsm_x4(al[mf][0], al[mf][1], al[mf][2], al[mf][3], addr + A_PLANE_SZ);
            }
            uint32_t bh[4][4], bl[4][4];
            #pragma unroll
            for (int p = 0; p < 4; p++) {
                int r = ks + (lane & 15);
                int cbytes = (warp_n * 64 + p * 16 + (lane >> 4) * 8) * 2;
                uint32_t addr = bb + OFF_B_TILE + r * B_STRIDE_B + cbytes;
                ldsm_x4_t(bh[p][0], bh[p][1], bh[p][2], bh[p][3], addr);
                ldsm_x4_t(bl[p][0], bl[p][1], bl[p][2], bl[p][3], addr + B_PLANE_SZ);
            }
            #pragma unroll
            for (int mf = 0; mf < 2; mf++) {
                #pragma unroll
                for (int nf = 0; nf < 8; nf++) {
                    const uint32_t* bhp = &bh[nf >> 1][(nf & 1) * 2];
                    const uint32_t* blp = &bl[nf >> 1][(nf & 1) * 2];
                    mma16816(acc[mf][nf], ah[mf], bhp);
                    mma16816(acc[mf][nf], ah[mf], blp);
                    mma16816(acc[mf][nf], al[mf], bhp);
                }
            }
        }
        __syncthreads();
    }

    float* __restrict__ C = &g_t[0];
    const int group = lane >> 2;
    const int col2  = (lane & 3) * 2;
    #pragma unroll
    for (int mf = 0; mf < 2; mf++) {
        int r0 = mBase + warp_m * 32 + mf * 16 + group;
        #pragma unroll
        for (int nf = 0; nf < 8; nf++) {
            int cidx = nBase + warp_n * 64 + nf * 8 + col2;
            if (r0 < M)
                *(float2*)(C + (size_t)r0 * Ng + cidx) = make_float2(acc[mf][nf][0], acc[mf][nf][1]);
            if (r0 + 8 < M)
                *(float2*)(C + (size_t)(r0 + 8) * Ng + cidx) = make_float2(acc[mf][nf][2], acc[mf][nf][3]);
        }
    }
}

// ---------------- SpMM (feature-chunked, 256 ch per launch, 64 threads) ----------------
// out[d, coff:coff+256] = [relu](sum w_e*t[src] + dinv^2*t[d] + bias) [+ residual]
// SPLITOUT: write bf16 hi/lo planes to g_sa[osel]; else fp32 to OutExt (C_OUT layout).
template <bool RES, bool SPLITOUT, bool RELU>
__global__ void k_spmm_c(const float* __restrict__ bias, int rsel, int osel,
                         float* __restrict__ OutExt, int coff, int C) {
    constexpr int NT = 64;
    const float* __restrict__ T = &g_t[0];

    const int node = blockIdx.x;
    const int tid  = threadIdx.x;

    __shared__ int   s_src[NT];
    __shared__ float s_w[NT];

    const int ch = coff + tid * 4;

    float di = g_dinv[node];
    float w0 = di * di;
    float4 v = *(const float4*)(T + (size_t)node * C + ch);
    float4 acc = make_float4(v.x * w0, v.y * w0, v.z * w0, v.w * w0);

    int beg = g_rowstart[node];
    int end = g_rowstart[node + 1];

    for (int j0 = beg; j0 < end; j0 += NT) {
        int n = min(NT, end - j0);
        __syncthreads();
        if (tid < n) {
            s_src[tid] = g_csr_src[j0 + tid];
            s_w[tid]   = g_csr_w[j0 + tid];
        }
        __syncthreads();
        for (int j = 0; j < n; j++) {
            int   s = s_src[j];
            float w = s_w[j];
            float4 hv = *(const float4*)(T + (size_t)s * C + ch);
            acc.x = fmaf(w, hv.x, acc.x);
            acc.y = fmaf(w, hv.y, acc.y);
            acc.z = fmaf(w, hv.z, acc.z);
            acc.w = fmaf(w, hv.w, acc.w);
        }
    }

    float4 b4 = *(const float4*)(bias + ch);
    acc.x += b4.x; acc.y += b4.y; acc.z += b4.z; acc.w += b4.w;
    if (RELU) {
        acc.x = fmaxf(acc.x, 0.f); acc.y = fmaxf(acc.y, 0.f);
        acc.z = fmaxf(acc.z, 0.f); acc.w = fmaxf(acc.w, 0.f);
    }

    if (SPLITOUT) {
        size_t off = (size_t)node * C_H + ch;
        if (RES) {
            const __nv_bfloat16* rh = &g_sa[rsel][0][0];
            const __nv_bfloat16* rl = &g_sa[rsel][1][0];
            acc.x += __bfloat162float(rh[off + 0]) + __bfloat162float(rl[off + 0]);
            acc.y += __bfloat162float(rh[off + 1]) + __bfloat162float(rl[off + 1]);
            acc.z += __bfloat162float(rh[off + 2]) + __bfloat162float(rl[off + 2]);
            acc.w += __bfloat162float(rh[off + 3]) + __bfloat162float(rl[off + 3]);
        }
        __nv_bfloat16 h0 = __float2bfloat16_rn(acc.x), h1 = __float2bfloat16_rn(acc.y);
        __nv_bfloat16 h2 = __float2bfloat16_rn(acc.z), h3 = __float2bfloat16_rn(acc.w);
        __nv_bfloat16 l0 = __float2bfloat16_rn(acc.x - __bfloat162float(h0));
        __nv_bfloat16 l1 = __float2bfloat16_rn(acc.y - __bfloat162float(h1));
        __nv_bfloat16 l2 = __float2bfloat16_rn(acc.z - __bfloat162float(h2));
        __nv_bfloat16 l3 = __float2bfloat16_rn(acc.w - __bfloat162float(h3));
        __nv_bfloat162 hp0 = {h0, h1}, hp1 = {h2, h3}, lp0 = {l0, l1}, lp1 = {l2, l3};
        // evict-first streaming stores: keep gather set resident in L2
        __stcs((uint2*)&g_sa[osel][0][off],
               make_uint2(*(uint32_t*)&hp0, *(uint32_t*)&hp1));
        __stcs((uint2*)&g_sa[osel][1][off],
               make_uint2(*(uint32_t*)&lp0, *(uint32_t*)&lp1));
    } else {
        __stcs((float4*)(OutExt + (size_t)node * C_OUT + ch), acc);
    }
}

// ---------------- launch ----------------
extern "C" void kernel_launch(void* const* d_in, const int* in_sizes, int n_in,
                              void* d_out, int out_size) {
    const float* x  = (const float*)d_in[0];
    const int*   ei = (const int*)d_in[1];
    const float* W1 = (const float*)d_in[2];
    const float* b1 = (const float*)d_in[3];
    const float* Wr = (const float*)d_in[4];
    const float* br = (const float*)d_in[5];
    const float* Wx = (const float*)d_in[6];
    const float* bx = (const float*)d_in[7];
    float* out = (float*)d_out;

    cudaFuncSetAttribute(k_gemm_tc, cudaFuncAttributeMaxDynamicSharedMemorySize,
                         GEMM_SMEM);

    // ---- CSR build ----
    k_detect    <<<1, 256>>>(ei);
    k_zero      <<<(NN + 255) / 256, 256>>>();
    k_count     <<<(NE + 255) / 256, 256>>>(ei);
    k_dinv      <<<(NN + 255) / 256, 256>>>();
    k_scan_local<<<SCAN_NB, 1024>>>();
    k_scan_sums <<<1, 64>>>();
    k_scan_add  <<<SCAN_NB, 1024>>>();
    k_scatter   <<<(NE + 255) / 256, 256>>>(ei);

    // ---- splits ----
    k_split_x<<<(int)(((size_t)NN * C_H + 255) / 256), 256>>>(x);
    k_split_w<<<(KDIM * C_H + 255) / 256, 256>>>(W1, 0, C_H);
    k_split_w<<<(KDIM * C_H + 255) / 256, 256>>>(Wr, 1, C_H);
    k_split_w<<<(KDIM * C_OUT + 255) / 256, 256>>>(Wx, 2, C_OUT);

    dim3 grid512(C_H / 128, (NN + 127) / 128);
    dim3 grid256(C_OUT / 128, (NN + 127) / 128);

    // layer 0: h0 = relu(A (x@W1) + b1) -> split sel 0
    k_gemm_tc<<<grid512, 256, GEMM_SMEM>>>(2, 0, NN, C_H);
    k_spmm_c<false, true, true><<<NN, 64>>>(b1, 0, 0, nullptr, 0,   C_H);
    k_spmm_c<false, true, true><<<NN, 64>>>(b1, 0, 0, nullptr, 256, C_H);

    // 4 residual layers
    int cur = 0;
    for (int l = 0; l < 4; l++) {
        int nxt = cur ^ 1;
        k_gemm_tc<<<grid512, 256, GEMM_SMEM>>>(cur, 1, NN, C_H);
        k_spmm_c<true, true, true><<<NN, 64>>>(br, cur, nxt, nullptr, 0,   C_H);
        k_spmm_c<true, true, true><<<NN, 64>>>(br, cur, nxt, nullptr, 256, C_H);
        cur = nxt;
    }

    // final: out = A (h@Wx) + bx   (single 256-ch chunk, no relu)
    k_gemm_tc<<<grid256, 256, GEMM_SMEM>>>(cur, 2, NN, C_OUT);
    k_spmm_c<false, false, false><<<NN, 64>>>(bx, 0, 0, out, 0, C_OUT);
}